// round 8
// baseline (speedup 1.0000x reference)
#include <cuda_runtime.h>
#include <cuda_fp16.h>

#define NB 8192
#define NT 16
#define NK 512
#define ND 128
#define TILE_B 128
#define NBT (NB/TILE_B)          // 64 row tiles
#define CHN 128                  // codes per chunk
#define NCH (NK/CHN)             // 4 chunks
#define CSCALE 2048.0f           // codebook pre-scale (exact power of 2)
#define DSCL 0.0009765625f       // 2/2048 : acc -> 2*dot (exact)
#define EPS 1e-4f                // candidate window (~25 sigma of approx error)
#define LOSS_SCALE 1048576.0

typedef unsigned u32;
typedef unsigned long long u64;

// smem map (bytes)
#define SM_Z2   0                         // 128 f
#define SM_C2   512                       // 512 f
#define SM_RED  2560                      // 256 double
#define SM_BK   4608                      // 128 int
#define SM_FBN  5120                      // int
#define SM_FBR  5124                      // 128 int
#define SM_FBB  5640                      // u64 (8-aligned)
#define SM_A    5760                      // 1 plane zh: 128*136 half
#define APS     (128*136*2)               // 34816 bytes per plane
#define SM_B    (SM_A + APS)              // 2 bufs * 2 planes (ch, cl)
#define SM_TOT  (SM_B + 4*APS)            // 179840

// scratch: pre-split scaled codebook, fp16 [T][chunk][plane][128][128]
__device__ __half g_cs[NT][NCH][2][CHN][ND];
__device__ float  g_csq[NT * NK];
__device__ u64    g_loss;
__device__ int    g_used[NT * NK];

__device__ __forceinline__ u32 s2u(const void* p) {
    u32 a;
    asm("{ .reg .u64 t; cvta.to.shared.u64 t, %1; cvt.u32.u64 %0, t; }" : "=r"(a) : "l"(p));
    return a;
}
__device__ __forceinline__ void ldsm4(u32* r, u32 a) {
    asm volatile("ldmatrix.sync.aligned.m8n8.x4.shared.b16 {%0,%1,%2,%3}, [%4];"
        : "=r"(r[0]), "=r"(r[1]), "=r"(r[2]), "=r"(r[3]) : "r"(a));
}
__device__ __forceinline__ void mma16816(float* c, const u32* a, u32 b0, u32 b1) {
    asm volatile("mma.sync.aligned.m16n8k16.row.col.f32.f16.f16.f32 "
        "{%0,%1,%2,%3}, {%4,%5,%6,%7}, {%8,%9}, {%0,%1,%2,%3};"
        : "+f"(c[0]), "+f"(c[1]), "+f"(c[2]), "+f"(c[3])
        : "r"(a[0]), "r"(a[1]), "r"(a[2]), "r"(a[3]), "r"(b0), "r"(b1));
}
__device__ __forceinline__ void cpa16(u32 dst, const void* src) {
    asm volatile("cp.async.cg.shared.global [%0], [%1], 16;" :: "r"(dst), "l"(src));
}

// NEON-order sum of squares (bit-exact match to the R4-passing kernel)
__device__ __forceinline__ float sq_neon(const float* zr) {
    float s0 = 0.f, s1 = 0.f, s2 = 0.f, s3 = 0.f;
    #pragma unroll 8
    for (int d = 0; d < ND; d += 4) {
        s0 = __fadd_rn(s0, __fmul_rn(zr[d+0], zr[d+0]));
        s1 = __fadd_rn(s1, __fmul_rn(zr[d+1], zr[d+1]));
        s2 = __fadd_rn(s2, __fmul_rn(zr[d+2], zr[d+2]));
        s3 = __fadd_rn(s3, __fmul_rn(zr[d+3], zr[d+3]));
    }
    return __fadd_rn(__fadd_rn(s0, s2), __fadd_rn(s1, s3));
}

// Exact R4 distance recipe: even/odd fma chains (== FFMA2), dot=lo+hi,
// dist = fl(fl(z2 - 2*dot) + c2). 2*dot exact.
__device__ __forceinline__ float exact_dist(const float* __restrict__ z,
                                            const float* __restrict__ c,
                                            float z2, float c2) {
    float lo = 0.f, hi = 0.f;
    #pragma unroll 16
    for (int i = 0; i < 64; i++) {
        lo = __fmaf_rn(z[2*i],   c[2*i],   lo);
        hi = __fmaf_rn(z[2*i+1], c[2*i+1], hi);
    }
    float dot = __fadd_rn(lo, hi);
    return __fadd_rn(__fsub_rn(z2, 2.0f * dot), c2);
}

// ---- prep: zero globals, split scaled codebook to fp16 pairs, c^2 ----
__global__ __launch_bounds__(256) void vq_prep(const float* __restrict__ cbk) {
    const int tid = threadIdx.x, ch = blockIdx.x, t = blockIdx.y;
    if (ch == 0 && t == 0) {
        if (tid == 0) g_loss = 0ull;
        for (int i = tid; i < NT*NK; i += 256) g_used[i] = 0;
    }
    const int k0 = ch * CHN;
    if (tid < CHN)
        g_csq[t*NK + k0 + tid] = sq_neon(cbk + ((size_t)t*NK + k0 + tid)*ND);
    for (int j = 0; j < 16; j++) {
        int i = tid + 256*j;                 // 4096 float4 tasks
        int r = i >> 5, q = i & 31;
        float4 v = *(const float4*)(cbk + ((size_t)t*NK + k0 + r)*ND + 4*q);
        float sx = v.x*CSCALE, sy = v.y*CSCALE, sz = v.z*CSCALE, sw = v.w*CSCALE;
        __half hx = __float2half_rn(sx), hy = __float2half_rn(sy);
        __half hz = __float2half_rn(sz), hw = __float2half_rn(sw);
        __half lx = __float2half_rn(sx - __half2float(hx));
        __half ly = __float2half_rn(sy - __half2float(hy));
        __half lz = __float2half_rn(sz - __half2float(hz));
        __half lw = __float2half_rn(sw - __half2float(hw));
        __half2* ph = (__half2*)&g_cs[t][ch][0][r][4*q];
        __half2* pl = (__half2*)&g_cs[t][ch][1][r][4*q];
        ph[0] = __halves2half2(hx, hy); ph[1] = __halves2half2(hz, hw);
        pl[0] = __halves2half2(lx, ly); pl[1] = __halves2half2(lz, lw);
    }
}

// ---- main: HMMA candidate GEMM + exact rescore + outputs ----
__global__ __launch_bounds__(256, 1)
void vq_main(const float* __restrict__ z_e, const float* __restrict__ cbk,
             float* __restrict__ out)
{
    extern __shared__ unsigned char sm[];
    const u32 sb = s2u(sm);
    const int tid = threadIdx.x, lane = tid & 31, wid = tid >> 5;
    const int t = blockIdx.y, bt = blockIdx.x, b0 = bt * TILE_B;
    const int wm = (wid >> 1) * 32, wcol = wid & 1, wn0 = wcol * 64;

    float*  z2s = (float*)(sm + SM_Z2);
    float*  c2s = (float*)(sm + SM_C2);
    double* red = (double*)(sm + SM_RED);
    int*    bks = (int*)(sm + SM_BK);
    int*    fbn = (int*)(sm + SM_FBN);
    int*    fbr = (int*)(sm + SM_FBR);
    u64*    fbb = (u64*)(sm + SM_FBB);

    if (tid == 0) *fbn = 0;

    // issue B chunk 0 and 1 loads (cp.async, two commit groups)
    #pragma unroll 1
    for (int pre = 0; pre < 2; pre++) {
        for (int j = 0; j < 16; j++) {
            int i = tid + 256*j;             // 4096 x 16B per chunk (2 planes)
            int pl = i >> 11, r = (i >> 4) & 127, sg = i & 15;
            u32 dst = sb + SM_B + (u32)pre*(2*APS) + (u32)pl*APS + (u32)r*272 + (u32)sg*16;
            cpa16(dst, (const char*)&g_cs[t][pre][pl][r][0] + sg*16);
        }
        asm volatile("cp.async.commit_group;" ::: "memory");
    }

    // A tile: load z fp32, round to fp16 zh plane in smem (single plane)
    {
        __half* zh = (__half*)(sm + SM_A);
        for (int j = 0; j < 16; j++) {
            int i = tid + 256*j;
            int r = i >> 5, q = i & 31;
            float4 v = *(const float4*)(z_e + ((size_t)(b0+r)*NT + t)*ND + 4*q);
            int o = r*136 + 4*q;
            *(__half2*)(zh + o)     = __halves2half2(__float2half_rn(v.x), __float2half_rn(v.y));
            *(__half2*)(zh + o + 2) = __halves2half2(__float2half_rn(v.z), __float2half_rn(v.w));
        }
    }
    for (int i = tid; i < NK; i += 256) c2s[i] = g_csq[t*NK + i];
    if (tid < TILE_B)
        z2s[tid] = sq_neon(z_e + ((size_t)(b0+tid)*NT + t)*ND);

    // per-thread ldmatrix base addresses
    const u32 aad = sb + SM_A + (u32)(wm + (lane & 15))*272 + (u32)(lane >> 4)*16;
    const u32 bn  = (u32)(wn0 + (lane & 7) + ((lane >> 4) << 3));
    const u32 bad0 = sb + SM_B + bn*272 + (u32)((lane >> 3) & 1)*16;

    // per-thread top-2 keys for each of the thread's 4 row-fragments
    u64 bst0[2][2], bst1[2][2];
    #pragma unroll
    for (int a = 0; a < 2; a++)
        #pragma unroll
        for (int b = 0; b < 2; b++) { bst0[a][b] = ~0ull; bst1[a][b] = ~0ull; }

    #pragma unroll 1
    for (int c = 0; c < NCH; c++) {
        if (c < NCH-1) asm volatile("cp.async.wait_group 1;" ::: "memory");
        else           asm volatile("cp.async.wait_group 0;" ::: "memory");
        __syncthreads();

        float acc[2][8][4];
        #pragma unroll
        for (int mf = 0; mf < 2; mf++)
            #pragma unroll
            for (int nf = 0; nf < 8; nf++)
                #pragma unroll
                for (int e = 0; e < 4; e++) acc[mf][nf][e] = 0.f;

        const u32 bufo = (u32)(c & 1) * (2*APS);
        #pragma unroll
        for (int pair = 0; pair < 2; pair++) {         // (zh,ch), (zh,cl)
            const u32 ab = aad;
            const u32 bb = bad0 + bufo + (u32)pair*APS;
            #pragma unroll
            for (int ks = 0; ks < 8; ks++) {
                u32 a[2][4];
                ldsm4(a[0], ab + (u32)ks*32);
                ldsm4(a[1], ab + 16u*272 + (u32)ks*32);
                #pragma unroll
                for (int g = 0; g < 4; g++) {
                    u32 bb4[4];
                    ldsm4(bb4, bb + (u32)g*16*272 + (u32)ks*32);
                    mma16816(acc[0][2*g],   a[0], bb4[0], bb4[1]);
                    mma16816(acc[0][2*g+1], a[0], bb4[2], bb4[3]);
                    mma16816(acc[1][2*g],   a[1], bb4[0], bb4[1]);
                    mma16816(acc[1][2*g+1], a[1], bb4[2], bb4[3]);
                }
            }
        }

        // approx distances + running per-thread top-2 (u64 key: dist bits || idx)
        #pragma unroll
        for (int mf = 0; mf < 2; mf++)
            #pragma unroll
            for (int h = 0; h < 2; h++) {
                float z2v = z2s[wm + 16*mf + (lane >> 2) + 8*h];
                u64 b0k = bst0[mf][h], b1k = bst1[mf][h];
                #pragma unroll
                for (int nf = 0; nf < 8; nf++) {
                    int colg = c*CHN + wn0 + 8*nf + (lane & 3)*2;
                    #pragma unroll
                    for (int e = 0; e < 2; e++) {
                        float a = acc[mf][nf][2*h + e];
                        float dist = __fadd_rn(__fsub_rn(z2v, __fmul_rn(a, DSCL)), c2s[colg + e]);
                        u64 key = ((u64)__float_as_uint(dist) << 32) | (u32)(colg + e);
                        if (key < b1k) {
                            if (key < b0k) { b1k = b0k; b0k = key; }
                            else b1k = key;
                        }
                    }
                }
                bst0[mf][h] = b0k; bst1[mf][h] = b1k;
            }

        __syncthreads();                     // all warps done reading buf before refill
        if (c + 2 < NCH) {
            for (int j = 0; j < 16; j++) {
                int i = tid + 256*j;
                int pl = i >> 11, r = (i >> 4) & 127, sg = i & 15;
                u32 dst = sb + SM_B + bufo + (u32)pl*APS + (u32)r*272 + (u32)sg*16;
                cpa16(dst, (const char*)&g_cs[t][c+2][pl][r][0] + sg*16);
            }
            asm volatile("cp.async.commit_group;" ::: "memory");
        }
    }

    // gather: 16 keys per row (8 threads x top-2), into dead B-buffer smem
    u64* cand = (u64*)(sm + SM_B);           // 128 rows * 16 keys = 16 KB
    #pragma unroll
    for (int mf = 0; mf < 2; mf++)
        #pragma unroll
        for (int h = 0; h < 2; h++) {
            int row = wm + 16*mf + 8*h + (lane >> 2);
            int slot = wcol*8 + (lane & 3)*2;
            cand[row*16 + slot]     = bst0[mf][h];
            cand[row*16 + slot + 1] = bst1[mf][h];
        }
    __syncthreads();

    // resolve per row: find approx min, certify, exact-rescore candidates
    if (tid < TILE_B) {
        const int row = tid, b = b0 + row;
        const u64* ck = cand + row*16;
        u64 mn = ck[0];
        #pragma unroll
        for (int j = 1; j < 16; j++) if (ck[j] < mn) mn = ck[j];
        const float thr = __uint_as_float((u32)(mn >> 32)) + EPS;

        bool fb = false;
        #pragma unroll
        for (int p = 0; p < 8; p++)
            if (__uint_as_float((u32)(ck[2*p+1] >> 32)) <= thr) fb = true;

        if (fb) {
            int s = atomicAdd(fbn, 1);
            fbr[s] = row;
        } else {
            int ncand = 0;
            #pragma unroll
            for (int j = 0; j < 16; j++)
                if (__uint_as_float((u32)(ck[j] >> 32)) <= thr) ncand++;
            if (ncand <= 1) {
                bks[row] = (int)(mn & 0xffffffffu);
            } else {
                const float* zp = z_e + ((size_t)b*NT + t)*ND;
                const float z2 = z2s[row];
                u64 ebest = ~0ull;
                for (int j = 0; j < 16; j++) {
                    if (__uint_as_float((u32)(ck[j] >> 32)) > thr) continue;
                    int k = (int)(ck[j] & 0xffffffffu);
                    float ed = exact_dist(zp, cbk + ((size_t)t*NK + k)*ND, z2, c2s[k]);
                    u64 ek = ((u64)__float_as_uint(ed) << 32) | (u32)k;
                    if (ek < ebest) ebest = ek;
                }
                bks[row] = (int)(ebest & 0xffffffffu);
            }
        }
    }
    __syncthreads();

    // cooperative exact fallback for uncertified rows (rare)
    {
        const int nfb = *fbn;
        for (int f = 0; f < nfb; f++) {
            if (tid == 0) *fbb = ~0ull;
            __syncthreads();
            const int row = fbr[f], b = b0 + row;
            const float* zp = z_e + ((size_t)b*NT + t)*ND;
            const float z2 = z2s[row];
            u64 loc = ~0ull;
            #pragma unroll
            for (int q = 0; q < 2; q++) {
                int k = tid + 256*q;
                float ed = exact_dist(zp, cbk + ((size_t)t*NK + k)*ND, z2, c2s[k]);
                u64 ek = ((u64)__float_as_uint(ed) << 32) | (u32)k;
                if (ek < loc) loc = ek;
            }
            #pragma unroll
            for (int off = 16; off >= 1; off >>= 1) {
                u64 o = __shfl_xor_sync(0xffffffffu, loc, off);
                if (o < loc) loc = o;
            }
            if (lane == 0) atomicMin(fbb, loc);
            __syncthreads();
            if (tid == 0) bks[row] = (int)(*fbb & 0xffffffffu);
        }
    }
    __syncthreads();

    // tokens + usage
    if (tid < TILE_B) {
        int bk = bks[tid], b = b0 + tid;
        out[(size_t)NB*NT*ND + (size_t)b*NT + t] = (float)bk;
        g_used[t*NK + bk] = 1;
    }
    __syncthreads();

    // z_q_st + loss: 2 threads per row (64 floats each), R4-identical rounding
    {
        int row = tid >> 1, half = tid & 1;
        int b = b0 + row, bk = bks[row];
        const float4* zr = (const float4*)(z_e + ((size_t)b*NT + t)*ND + half*64);
        const float4* cr = (const float4*)(cbk + ((size_t)t*NK + bk)*ND + half*64);
        float4* orow = (float4*)(out + ((size_t)b*NT + t)*ND + half*64);
        double ls = 0.0;
        #pragma unroll 4
        for (int q = 0; q < 16; q++) {
            float4 zv = zr[q], cv = cr[q], ov;
            ov.x = __fadd_rn(zv.x, __fsub_rn(cv.x, zv.x)); { float d = __fsub_rn(zv.x, cv.x); ls += (double)__fmul_rn(d, d); }
            ov.y = __fadd_rn(zv.y, __fsub_rn(cv.y, zv.y)); { float d = __fsub_rn(zv.y, cv.y); ls += (double)__fmul_rn(d, d); }
            ov.z = __fadd_rn(zv.z, __fsub_rn(cv.z, zv.z)); { float d = __fsub_rn(zv.z, cv.z); ls += (double)__fmul_rn(d, d); }
            ov.w = __fadd_rn(zv.w, __fsub_rn(cv.w, zv.w)); { float d = __fsub_rn(zv.w, cv.w); ls += (double)__fmul_rn(d, d); }
            orow[q] = ov;
        }
        red[tid] = ls;
    }
    __syncthreads();
    for (int s = 128; s > 0; s >>= 1) {
        if (tid < s) red[tid] += red[tid + s];
        __syncthreads();
    }
    if (tid == 0) {
        long long q = __double2ll_rn(red[0] * LOSS_SCALE);
        atomicAdd(&g_loss, (u64)q);
    }
}

__global__ void vq_fin(float* __restrict__ out) {
    __shared__ int cnt[256];
    int tid = threadIdx.x;
    int c = 0;
    for (int i = tid; i < NT*NK; i += 256) c += g_used[i];
    cnt[tid] = c;
    __syncthreads();
    for (int s = 128; s > 0; s >>= 1) {
        if (tid < s) cnt[tid] += cnt[tid + s];
        __syncthreads();
    }
    if (tid == 0) {
        double ls = (double)g_loss / LOSS_SCALE;
        float vql = (float)(0.25 * ls / ((double)NB * NT * ND));
        size_t base = (size_t)NB*NT*ND + (size_t)NB*NT;
        out[base]     = vql;
        out[base + 1] = (float)cnt[0] / (float)(NT * NK);
    }
}

extern "C" void kernel_launch(void* const* d_in, const int* in_sizes, int n_in,
                              void* d_out, int out_size)
{
    const float* z_e = (const float*)d_in[0];   // (B, T, D) fp32
    const float* cbk = (const float*)d_in[1];   // (T, K, D) fp32
    float* out = (float*)d_out;

    cudaFuncSetAttribute(vq_main, cudaFuncAttributeMaxDynamicSharedMemorySize, SM_TOT);

    vq_prep<<<dim3(NCH, NT), 256>>>(cbk);
    vq_main<<<dim3(NBT, NT), 256, SM_TOT>>>(z_e, cbk, out);
    vq_fin<<<1, 256>>>(out);
}

// round 12
// speedup vs baseline: 1.0532x; 1.0532x over previous
#include <cuda_runtime.h>
#include <cuda_fp16.h>

#define NB 8192
#define NT 16
#define NK 512
#define ND 128
#define TILE_B 128
#define NBT (NB/TILE_B)          // 64 row tiles
#define CHN 128                  // codes per chunk
#define NCH (NK/CHN)             // 4 chunks
#define CSCALE 2048.0f           // codebook pre-scale (exact power of 2)
#define DSCL 0.0009765625f       // 2/2048 : acc -> 2*dot (exact)
#define EPS 1e-4f                // candidate window (~25 sigma of approx error)
#define LOSS_SCALE 1048576.0
#define NTH 512

typedef unsigned u32;
typedef unsigned long long u64;

// smem map (bytes)
#define SM_Z2   0                         // 128 f
#define SM_C2   512                       // 512 f
#define SM_RED  2560                      // 512 double
#define SM_BK   6656                      // 128 int
#define SM_FBN  7168                      // int
#define SM_FBR  7172                      // 128 int
#define SM_FBB  7688                      // u64 (8-aligned)
#define SM_A    7712                      // 1 plane zh: 128*136 half
#define APS     (128*136*2)               // 34816 bytes per plane
#define SM_B    (SM_A + APS)              // 2 bufs * 2 planes (ch, cl)
#define SM_TOT  (SM_B + 4*APS)            // 181792

// scratch: pre-split scaled codebook, fp16 [T][chunk][plane][128][128]
__device__ __half g_cs[NT][NCH][2][CHN][ND];
__device__ float  g_csq[NT * NK];
__device__ u64    g_loss;
__device__ int    g_used[NT * NK];

__device__ __forceinline__ u32 s2u(const void* p) {
    u32 a;
    asm("{ .reg .u64 t; cvta.to.shared.u64 t, %1; cvt.u32.u64 %0, t; }" : "=r"(a) : "l"(p));
    return a;
}
__device__ __forceinline__ void ldsm4(u32* r, u32 a) {
    asm volatile("ldmatrix.sync.aligned.m8n8.x4.shared.b16 {%0,%1,%2,%3}, [%4];"
        : "=r"(r[0]), "=r"(r[1]), "=r"(r[2]), "=r"(r[3]) : "r"(a));
}
__device__ __forceinline__ void mma16816(float* c, const u32* a, u32 b0, u32 b1) {
    asm volatile("mma.sync.aligned.m16n8k16.row.col.f32.f16.f16.f32 "
        "{%0,%1,%2,%3}, {%4,%5,%6,%7}, {%8,%9}, {%0,%1,%2,%3};"
        : "+f"(c[0]), "+f"(c[1]), "+f"(c[2]), "+f"(c[3])
        : "r"(a[0]), "r"(a[1]), "r"(a[2]), "r"(a[3]), "r"(b0), "r"(b1));
}
__device__ __forceinline__ void cpa16(u32 dst, const void* src) {
    asm volatile("cp.async.cg.shared.global [%0], [%1], 16;" :: "r"(dst), "l"(src));
}

// NEON-order sum of squares (bit-exact match to the R4-passing kernel)
__device__ __forceinline__ float sq_neon(const float* zr) {
    float s0 = 0.f, s1 = 0.f, s2 = 0.f, s3 = 0.f;
    #pragma unroll 8
    for (int d = 0; d < ND; d += 4) {
        s0 = __fadd_rn(s0, __fmul_rn(zr[d+0], zr[d+0]));
        s1 = __fadd_rn(s1, __fmul_rn(zr[d+1], zr[d+1]));
        s2 = __fadd_rn(s2, __fmul_rn(zr[d+2], zr[d+2]));
        s3 = __fadd_rn(s3, __fmul_rn(zr[d+3], zr[d+3]));
    }
    return __fadd_rn(__fadd_rn(s0, s2), __fadd_rn(s1, s3));
}

// Exact R4 distance recipe: even/odd fma chains (== FFMA2), dot=lo+hi,
// dist = fl(fl(z2 - 2*dot) + c2). 2*dot exact.
__device__ __forceinline__ float exact_dist(const float* __restrict__ z,
                                            const float* __restrict__ c,
                                            float z2, float c2) {
    float lo = 0.f, hi = 0.f;
    #pragma unroll 16
    for (int i = 0; i < 64; i++) {
        lo = __fmaf_rn(z[2*i],   c[2*i],   lo);
        hi = __fmaf_rn(z[2*i+1], c[2*i+1], hi);
    }
    float dot = __fadd_rn(lo, hi);
    return __fadd_rn(__fsub_rn(z2, 2.0f * dot), c2);
}

// ---- prep: zero globals, split scaled codebook to fp16 pairs, c^2 ----
__global__ __launch_bounds__(256) void vq_prep(const float* __restrict__ cbk) {
    const int tid = threadIdx.x, ch = blockIdx.x, t = blockIdx.y;
    if (ch == 0 && t == 0) {
        if (tid == 0) g_loss = 0ull;
        for (int i = tid; i < NT*NK; i += 256) g_used[i] = 0;
    }
    const int k0 = ch * CHN;
    if (tid < CHN)
        g_csq[t*NK + k0 + tid] = sq_neon(cbk + ((size_t)t*NK + k0 + tid)*ND);
    for (int j = 0; j < 16; j++) {
        int i = tid + 256*j;                 // 4096 float4 tasks
        int r = i >> 5, q = i & 31;
        float4 v = *(const float4*)(cbk + ((size_t)t*NK + k0 + r)*ND + 4*q);
        float sx = v.x*CSCALE, sy = v.y*CSCALE, sz = v.z*CSCALE, sw = v.w*CSCALE;
        __half hx = __float2half_rn(sx), hy = __float2half_rn(sy);
        __half hz = __float2half_rn(sz), hw = __float2half_rn(sw);
        __half lx = __float2half_rn(sx - __half2float(hx));
        __half ly = __float2half_rn(sy - __half2float(hy));
        __half lz = __float2half_rn(sz - __half2float(hz));
        __half lw = __float2half_rn(sw - __half2float(hw));
        __half2* ph = (__half2*)&g_cs[t][ch][0][r][4*q];
        __half2* pl = (__half2*)&g_cs[t][ch][1][r][4*q];
        ph[0] = __halves2half2(hx, hy); ph[1] = __halves2half2(hz, hw);
        pl[0] = __halves2half2(lx, ly); pl[1] = __halves2half2(lz, lw);
    }
}

// ---- main: HMMA candidate GEMM + exact rescore + outputs ----
__global__ __launch_bounds__(NTH, 1)
void vq_main(const float* __restrict__ z_e, const float* __restrict__ cbk,
             float* __restrict__ out)
{
    extern __shared__ unsigned char sm[];
    const u32 sb = s2u(sm);
    const int tid = threadIdx.x, lane = tid & 31, wid = tid >> 5;
    const int t = blockIdx.y, bt = blockIdx.x, b0 = bt * TILE_B;
    const int wr = wid >> 2, wc = wid & 3;
    const int wm = wr * 32, wn0 = wc * 32;

    float*  z2s = (float*)(sm + SM_Z2);
    float*  c2s = (float*)(sm + SM_C2);
    double* red = (double*)(sm + SM_RED);
    int*    bks = (int*)(sm + SM_BK);
    int*    fbn = (int*)(sm + SM_FBN);
    int*    fbr = (int*)(sm + SM_FBR);
    u64*    fbb = (u64*)(sm + SM_FBB);

    if (tid == 0) *fbn = 0;

    // issue B chunk 0 and 1 loads (cp.async, two commit groups)
    #pragma unroll 1
    for (int pre = 0; pre < 2; pre++) {
        #pragma unroll
        for (int j = 0; j < 8; j++) {
            int i = tid + NTH*j;             // 4096 x 16B per chunk (2 planes)
            int pl = i >> 11, r = (i >> 4) & 127, sg = i & 15;
            u32 dst = sb + SM_B + (u32)pre*(2*APS) + (u32)pl*APS + (u32)r*272 + (u32)sg*16;
            cpa16(dst, (const char*)&g_cs[t][pre][pl][r][0] + sg*16);
        }
        asm volatile("cp.async.commit_group;" ::: "memory");
    }

    // A tile: load z fp32, round to fp16 zh plane in smem (single plane)
    {
        __half* zh = (__half*)(sm + SM_A);
        #pragma unroll
        for (int j = 0; j < 8; j++) {
            int i = tid + NTH*j;
            int r = i >> 5, q = i & 31;
            float4 v = *(const float4*)(z_e + ((size_t)(b0+r)*NT + t)*ND + 4*q);
            int o = r*136 + 4*q;
            *(__half2*)(zh + o)     = __halves2half2(__float2half_rn(v.x), __float2half_rn(v.y));
            *(__half2*)(zh + o + 2) = __halves2half2(__float2half_rn(v.z), __float2half_rn(v.w));
        }
    }
    if (tid < NK) c2s[tid] = g_csq[t*NK + tid];
    if (tid < TILE_B)
        z2s[tid] = sq_neon(z_e + ((size_t)(b0+tid)*NT + t)*ND);

    // per-thread ldmatrix base addresses
    const u32 aad0 = sb + SM_A + (u32)(wm + (lane & 15))*272 + (u32)(lane >> 4)*16;
    const u32 aad1 = aad0 + 16u*272;
    const u32 brow = (u32)(wn0 + (lane & 7) + ((lane >> 4) << 3));
    const u32 bof  = brow*272 + (u32)((lane >> 3) & 1)*16;   // col group 0 (+16*272 for group 1)

    // per-thread top-2 keys for each of the thread's 4 row-fragments
    u64 bst0[2][2], bst1[2][2];
    #pragma unroll
    for (int a = 0; a < 2; a++)
        #pragma unroll
        for (int b = 0; b < 2; b++) { bst0[a][b] = ~0ull; bst1[a][b] = ~0ull; }

    #pragma unroll 1
    for (int c = 0; c < NCH; c++) {
        if (c < NCH-1) asm volatile("cp.async.wait_group 1;" ::: "memory");
        else           asm volatile("cp.async.wait_group 0;" ::: "memory");
        __syncthreads();

        float acc[2][4][4];
        #pragma unroll
        for (int mf = 0; mf < 2; mf++)
            #pragma unroll
            for (int nf = 0; nf < 4; nf++)
                #pragma unroll
                for (int e = 0; e < 4; e++) acc[mf][nf][e] = 0.f;

        const u32 bufo = (u32)(c & 1) * (2*APS);
        const u32 pb0 = sb + SM_B + bufo + bof;          // plane0 (ch)
        const u32 pb1 = pb0 + APS;                       // plane1 (cl)

        // fragment double-buffers (hand-pipelined: volatile asm keeps source order)
        u32 af[2][2][4], b0f[2][2][4], b1f[2][4];
        ldsm4(af[0][0], aad0);
        ldsm4(af[0][1], aad1);
        ldsm4(b0f[0][0], pb0);
        ldsm4(b0f[0][1], pb0 + 16u*272);

        #pragma unroll
        for (int ks = 0; ks < 8; ks++) {
            const int cur = ks & 1, nxt = cur ^ 1;
            // prefetch plane1 B for this ks (used after 8 MMAs below)
            ldsm4(b1f[0], pb1 + (u32)ks*32);
            ldsm4(b1f[1], pb1 + 16u*272 + (u32)ks*32);
            // plane0 MMAs (frags loaded >= 8 MMA-issues ago)
            mma16816(acc[0][0], af[cur][0], b0f[cur][0][0], b0f[cur][0][1]);
            mma16816(acc[0][1], af[cur][0], b0f[cur][0][2], b0f[cur][0][3]);
            mma16816(acc[0][2], af[cur][0], b0f[cur][1][0], b0f[cur][1][1]);
            mma16816(acc[0][3], af[cur][0], b0f[cur][1][2], b0f[cur][1][3]);
            mma16816(acc[1][0], af[cur][1], b0f[cur][0][0], b0f[cur][0][1]);
            mma16816(acc[1][1], af[cur][1], b0f[cur][0][2], b0f[cur][0][3]);
            mma16816(acc[1][2], af[cur][1], b0f[cur][1][0], b0f[cur][1][1]);
            mma16816(acc[1][3], af[cur][1], b0f[cur][1][2], b0f[cur][1][3]);
            // prefetch next-ks A and plane0 B
            if (ks < 7) {
                ldsm4(af[nxt][0], aad0 + (u32)(ks+1)*32);
                ldsm4(af[nxt][1], aad1 + (u32)(ks+1)*32);
                ldsm4(b0f[nxt][0], pb0 + (u32)(ks+1)*32);
                ldsm4(b0f[nxt][1], pb0 + 16u*272 + (u32)(ks+1)*32);
            }
            // plane1 MMAs (A frags reused)
            mma16816(acc[0][0], af[cur][0], b1f[0][0], b1f[0][1]);
            mma16816(acc[0][1], af[cur][0], b1f[0][2], b1f[0][3]);
            mma16816(acc[0][2], af[cur][0], b1f[1][0], b1f[1][1]);
            mma16816(acc[0][3], af[cur][0], b1f[1][2], b1f[1][3]);
            mma16816(acc[1][0], af[cur][1], b1f[0][0], b1f[0][1]);
            mma16816(acc[1][1], af[cur][1], b1f[0][2], b1f[0][3]);
            mma16816(acc[1][2], af[cur][1], b1f[1][0], b1f[1][1]);
            mma16816(acc[1][3], af[cur][1], b1f[1][2], b1f[1][3]);
        }

        // approx distances + running per-thread top-2 (u64 key: dist bits || idx)
        #pragma unroll
        for (int mf = 0; mf < 2; mf++)
            #pragma unroll
            for (int h = 0; h < 2; h++) {
                float z2v = z2s[wm + 16*mf + (lane >> 2) + 8*h];
                u64 b0k = bst0[mf][h], b1k = bst1[mf][h];
                #pragma unroll
                for (int nf = 0; nf < 4; nf++) {
                    int colg = c*CHN + wn0 + 8*nf + (lane & 3)*2;
                    #pragma unroll
                    for (int e = 0; e < 2; e++) {
                        float a = acc[mf][nf][2*h + e];
                        float dist = __fadd_rn(__fsub_rn(z2v, __fmul_rn(a, DSCL)), c2s[colg + e]);
                        u64 key = ((u64)__float_as_uint(dist) << 32) | (u32)(colg + e);
                        if (key < b1k) {
                            if (key < b0k) { b1k = b0k; b0k = key; }
                            else b1k = key;
                        }
                    }
                }
                bst0[mf][h] = b0k; bst1[mf][h] = b1k;
            }

        __syncthreads();                     // all warps done reading buf before refill
        if (c + 2 < NCH) {
            #pragma unroll
            for (int j = 0; j < 8; j++) {
                int i = tid + NTH*j;
                int pl = i >> 11, r = (i >> 4) & 127, sg = i & 15;
                u32 dst = sb + SM_B + bufo + (u32)pl*APS + (u32)r*272 + (u32)sg*16;
                cpa16(dst, (const char*)&g_cs[t][c+2][pl][r][0] + sg*16);
            }
            asm volatile("cp.async.commit_group;" ::: "memory");
        }
    }

    // gather: 32 keys per row (16 threads x top-2), into dead B-buffer smem
    u64* cand = (u64*)(sm + SM_B);           // 128 rows * 32 keys = 32 KB
    #pragma unroll
    for (int mf = 0; mf < 2; mf++)
        #pragma unroll
        for (int h = 0; h < 2; h++) {
            int row = wm + 16*mf + 8*h + (lane >> 2);
            int slot = wc*8 + (lane & 3)*2;
            cand[row*32 + slot]     = bst0[mf][h];
            cand[row*32 + slot + 1] = bst1[mf][h];
        }
    __syncthreads();

    // resolve per row: find approx min, certify, exact-rescore candidates
    if (tid < TILE_B) {
        const int row = tid, b = b0 + row;
        const u64* ck = cand + row*32;
        u64 mn = ck[0];
        #pragma unroll
        for (int j = 1; j < 32; j++) if (ck[j] < mn) mn = ck[j];
        const float thr = __uint_as_float((u32)(mn >> 32)) + EPS;

        bool fb = false;
        #pragma unroll
        for (int p = 0; p < 16; p++)
            if (__uint_as_float((u32)(ck[2*p+1] >> 32)) <= thr) fb = true;

        if (fb) {
            int s = atomicAdd(fbn, 1);
            fbr[s] = row;
        } else {
            int ncand = 0;
            #pragma unroll
            for (int j = 0; j < 32; j++)
                if (__uint_as_float((u32)(ck[j] >> 32)) <= thr) ncand++;
            if (ncand <= 1) {
                bks[row] = (int)(mn & 0xffffffffu);
            } else {
                const float* zp = z_e + ((size_t)b*NT + t)*ND;
                const float z2 = z2s[row];
                u64 ebest = ~0ull;
                for (int j = 0; j < 32; j++) {
                    if (__uint_as_float((u32)(ck[j] >> 32)) > thr) continue;
                    int k = (int)(ck[j] & 0xffffffffu);
                    float ed = exact_dist(zp, cbk + ((size_t)t*NK + k)*ND, z2, c2s[k]);
                    u64 ek = ((u64)__float_as_uint(ed) << 32) | (u32)k;
                    if (ek < ebest) ebest = ek;
                }
                bks[row] = (int)(ebest & 0xffffffffu);
            }
        }
    }
    __syncthreads();

    // cooperative exact fallback for uncertified rows (rare): 512 codes, 1/thread
    {
        const int nfb = *fbn;
        for (int f = 0; f < nfb; f++) {
            if (tid == 0) *fbb = ~0ull;
            __syncthreads();
            const int row = fbr[f], b = b0 + row;
            const float* zp = z_e + ((size_t)b*NT + t)*ND;
            const float z2 = z2s[row];
            const int k = tid;
            float ed = exact_dist(zp, cbk + ((size_t)t*NK + k)*ND, z2, c2s[k]);
            u64 loc = ((u64)__float_as_uint(ed) << 32) | (u32)k;
            #pragma unroll
            for (int off = 16; off >= 1; off >>= 1) {
                u64 o = __shfl_xor_sync(0xffffffffu, loc, off);
                if (o < loc) loc = o;
            }
            if (lane == 0) atomicMin(fbb, loc);
            __syncthreads();
            if (tid == 0) bks[row] = (int)(*fbb & 0xffffffffu);
            __syncthreads();
        }
    }
    __syncthreads();

    // tokens + usage
    if (tid < TILE_B) {
        int bk = bks[tid], b = b0 + tid;
        out[(size_t)NB*NT*ND + (size_t)b*NT + t] = (float)bk;
        g_used[t*NK + bk] = 1;
    }
    __syncthreads();

    // z_q_st + loss: 4 threads per row (32 floats each), R4-identical rounding
    {
        int row = tid >> 2, quad = tid & 3;
        int b = b0 + row, bk = bks[row];
        const float4* zr = (const float4*)(z_e + ((size_t)b*NT + t)*ND + quad*32);
        const float4* cr = (const float4*)(cbk + ((size_t)t*NK + bk)*ND + quad*32);
        float4* orow = (float4*)(out + ((size_t)b*NT + t)*ND + quad*32);
        double ls = 0.0;
        #pragma unroll
        for (int q = 0; q < 8; q++) {
            float4 zv = zr[q], cv = cr[q], ov;
            ov.x = __fadd_rn(zv.x, __fsub_rn(cv.x, zv.x)); { float d = __fsub_rn(zv.x, cv.x); ls += (double)__fmul_rn(d, d); }
            ov.y = __fadd_rn(zv.y, __fsub_rn(cv.y, zv.y)); { float d = __fsub_rn(zv.y, cv.y); ls += (double)__fmul_rn(d, d); }
            ov.z = __fadd_rn(zv.z, __fsub_rn(cv.z, zv.z)); { float d = __fsub_rn(zv.z, cv.z); ls += (double)__fmul_rn(d, d); }
            ov.w = __fadd_rn(zv.w, __fsub_rn(cv.w, zv.w)); { float d = __fsub_rn(zv.w, cv.w); ls += (double)__fmul_rn(d, d); }
            orow[q] = ov;
        }
        red[tid] = ls;
    }
    __syncthreads();
    for (int s = 256; s > 0; s >>= 1) {
        if (tid < s) red[tid] += red[tid + s];
        __syncthreads();
    }
    if (tid == 0) {
        long long q = __double2ll_rn(red[0] * LOSS_SCALE);
        atomicAdd(&g_loss, (u64)q);
    }
}

__global__ void vq_fin(float* __restrict__ out) {
    __shared__ int cnt[256];
    int tid = threadIdx.x;
    int c = 0;
    for (int i = tid; i < NT*NK; i += 256) c += g_used[i];
    cnt[tid] = c;
    __syncthreads();
    for (int s = 128; s > 0; s >>= 1) {
        if (tid < s) cnt[tid] += cnt[tid + s];
        __syncthreads();
    }
    if (tid == 0) {
        double ls = (double)g_loss / LOSS_SCALE;
        float vql = (float)(0.25 * ls / ((double)NB * NT * ND));
        size_t base = (size_t)NB*NT*ND + (size_t)NB*NT;
        out[base]     = vql;
        out[base + 1] = (float)cnt[0] / (float)(NT * NK);
    }
}

extern "C" void kernel_launch(void* const* d_in, const int* in_sizes, int n_in,
                              void* d_out, int out_size)
{
    const float* z_e = (const float*)d_in[0];   // (B, T, D) fp32
    const float* cbk = (const float*)d_in[1];   // (T, K, D) fp32
    float* out = (float*)d_out;

    cudaFuncSetAttribute(vq_main, cudaFuncAttributeMaxDynamicSharedMemorySize, SM_TOT);

    vq_prep<<<dim3(NCH, NT), 256>>>(cbk);
    vq_main<<<dim3(NBT, NT), NTH, SM_TOT>>>(z_e, cbk, out);
    vq_fin<<<1, 256>>>(out);
}

// round 15
// speedup vs baseline: 1.3405x; 1.2728x over previous
#include <cuda_runtime.h>
#include <cuda_fp16.h>

#define NB 8192
#define NT 16
#define NK 512
#define ND 128
#define TILE_B 128
#define NBT (NB/TILE_B)          // 64 row tiles
#define CHN 128                  // codes per chunk
#define NCH (NK/CHN)             // 4 chunks
#define CSCALE 2048.0f           // codebook pre-scale (exact power of 2, keeps fp16 normal)
#define DSCL 0.0009765625f       // 2/2048 : acc -> 2*dot (exact)
#define EPS 4e-4f                // candidate window (>13 sigma of fp16 approx error)
#define LOSS_SCALE 1048576.0
#define NTH 512

typedef unsigned u32;
typedef unsigned long long u64;

// smem map (bytes)
#define SM_Z2   0                         // 128 f
#define SM_C2   512                       // 512 f
#define SM_RED  2560                      // 512 double
#define SM_BK   6656                      // 128 int
#define SM_FBN  7168                      // int
#define SM_FBR  7172                      // 128 int
#define SM_FBB  7688                      // u64 (8-aligned)
#define SM_A    7712                      // zh plane: 128*136 half
#define APS     (128*136*2)               // 34816 bytes per plane
#define SM_B    (SM_A + APS)              // 2 bufs * 1 plane (ch)
#define SM_TOT  (SM_B + 2*APS)            // 112160

// scratch: pre-scaled fp16 codebook [T][chunk][128][128]
__device__ __half g_cs[NT][NCH][CHN][ND];
__device__ float  g_csq[NT * NK];
__device__ u64    g_loss;
__device__ int    g_used[NT * NK];

__device__ __forceinline__ u32 s2u(const void* p) {
    u32 a;
    asm("{ .reg .u64 t; cvta.to.shared.u64 t, %1; cvt.u32.u64 %0, t; }" : "=r"(a) : "l"(p));
    return a;
}
__device__ __forceinline__ void ldsm4(u32* r, u32 a) {
    asm volatile("ldmatrix.sync.aligned.m8n8.x4.shared.b16 {%0,%1,%2,%3}, [%4];"
        : "=r"(r[0]), "=r"(r[1]), "=r"(r[2]), "=r"(r[3]) : "r"(a));
}
__device__ __forceinline__ void mma16816(float* c, const u32* a, u32 b0, u32 b1) {
    asm volatile("mma.sync.aligned.m16n8k16.row.col.f32.f16.f16.f32 "
        "{%0,%1,%2,%3}, {%4,%5,%6,%7}, {%8,%9}, {%0,%1,%2,%3};"
        : "+f"(c[0]), "+f"(c[1]), "+f"(c[2]), "+f"(c[3])
        : "r"(a[0]), "r"(a[1]), "r"(a[2]), "r"(a[3]), "r"(b0), "r"(b1));
}
__device__ __forceinline__ void cpa16(u32 dst, const void* src) {
    asm volatile("cp.async.cg.shared.global [%0], [%1], 16;" :: "r"(dst), "l"(src));
}

// NEON-order sum of squares (bit-exact match to the R4-passing kernel)
__device__ __forceinline__ float sq_neon(const float* zr) {
    float s0 = 0.f, s1 = 0.f, s2 = 0.f, s3 = 0.f;
    #pragma unroll 8
    for (int d = 0; d < ND; d += 4) {
        s0 = __fadd_rn(s0, __fmul_rn(zr[d+0], zr[d+0]));
        s1 = __fadd_rn(s1, __fmul_rn(zr[d+1], zr[d+1]));
        s2 = __fadd_rn(s2, __fmul_rn(zr[d+2], zr[d+2]));
        s3 = __fadd_rn(s3, __fmul_rn(zr[d+3], zr[d+3]));
    }
    return __fadd_rn(__fadd_rn(s0, s2), __fadd_rn(s1, s3));
}

// Exact R4 distance recipe: even/odd fma chains (== FFMA2), dot=lo+hi,
// dist = fl(fl(z2 - 2*dot) + c2). 2*dot exact.
__device__ __forceinline__ float exact_dist(const float* __restrict__ z,
                                            const float* __restrict__ c,
                                            float z2, float c2) {
    float lo = 0.f, hi = 0.f;
    #pragma unroll 16
    for (int i = 0; i < 64; i++) {
        lo = __fmaf_rn(z[2*i],   c[2*i],   lo);
        hi = __fmaf_rn(z[2*i+1], c[2*i+1], hi);
    }
    float dot = __fadd_rn(lo, hi);
    return __fadd_rn(__fsub_rn(z2, 2.0f * dot), c2);
}

// ---- prep: zero globals, scaled fp16 codebook, c^2 ----
__global__ __launch_bounds__(256) void vq_prep(const float* __restrict__ cbk) {
    const int tid = threadIdx.x, ch = blockIdx.x, t = blockIdx.y;
    if (ch == 0 && t == 0) {
        if (tid == 0) g_loss = 0ull;
        for (int i = tid; i < NT*NK; i += 256) g_used[i] = 0;
    }
    const int k0 = ch * CHN;
    if (tid < CHN)
        g_csq[t*NK + k0 + tid] = sq_neon(cbk + ((size_t)t*NK + k0 + tid)*ND);
    for (int j = 0; j < 16; j++) {
        int i = tid + 256*j;                 // 4096 float4 tasks
        int r = i >> 5, q = i & 31;
        float4 v = *(const float4*)(cbk + ((size_t)t*NK + k0 + r)*ND + 4*q);
        __half2* ph = (__half2*)&g_cs[t][ch][r][4*q];
        ph[0] = __halves2half2(__float2half_rn(v.x*CSCALE), __float2half_rn(v.y*CSCALE));
        ph[1] = __halves2half2(__float2half_rn(v.z*CSCALE), __float2half_rn(v.w*CSCALE));
    }
}

// ---- main: single-plane fp16 HMMA candidate GEMM + exact rescore + outputs ----
__global__ __launch_bounds__(NTH, 1)
void vq_main(const float* __restrict__ z_e, const float* __restrict__ cbk,
             float* __restrict__ out)
{
    extern __shared__ unsigned char sm[];
    const u32 sb = s2u(sm);
    const int tid = threadIdx.x, lane = tid & 31, wid = tid >> 5;
    const int t = blockIdx.y, bt = blockIdx.x, b0 = bt * TILE_B;
    const int wr = wid >> 2, wc = wid & 3;
    const int wm = wr * 32, wn0 = wc * 32;

    float*  z2s = (float*)(sm + SM_Z2);
    float*  c2s = (float*)(sm + SM_C2);
    double* red = (double*)(sm + SM_RED);
    int*    bks = (int*)(sm + SM_BK);
    int*    fbn = (int*)(sm + SM_FBN);
    int*    fbr = (int*)(sm + SM_FBR);
    u64*    fbb = (u64*)(sm + SM_FBB);

    if (tid == 0) *fbn = 0;

    // issue B chunk 0 and 1 loads (cp.async, two commit groups)
    #pragma unroll 1
    for (int pre = 0; pre < 2; pre++) {
        #pragma unroll
        for (int j = 0; j < 4; j++) {
            int i = tid + NTH*j;             // 2048 x 16B per chunk (1 plane)
            int r = i >> 4, sg = i & 15;
            u32 dst = sb + SM_B + (u32)pre*APS + (u32)r*272 + (u32)sg*16;
            cpa16(dst, (const char*)&g_cs[t][pre][r][0] + sg*16);
        }
        asm volatile("cp.async.commit_group;" ::: "memory");
    }

    // A tile: load z fp32, round to fp16 zh plane in smem
    {
        __half* zh = (__half*)(sm + SM_A);
        #pragma unroll
        for (int j = 0; j < 8; j++) {
            int i = tid + NTH*j;
            int r = i >> 5, q = i & 31;
            float4 v = *(const float4*)(z_e + ((size_t)(b0+r)*NT + t)*ND + 4*q);
            int o = r*136 + 4*q;
            *(__half2*)(zh + o)     = __halves2half2(__float2half_rn(v.x), __float2half_rn(v.y));
            *(__half2*)(zh + o + 2) = __halves2half2(__float2half_rn(v.z), __float2half_rn(v.w));
        }
    }
    if (tid < NK) c2s[tid] = g_csq[t*NK + tid];
    if (tid < TILE_B)
        z2s[tid] = sq_neon(z_e + ((size_t)(b0+tid)*NT + t)*ND);

    // per-thread ldmatrix base addresses
    const u32 aad0 = sb + SM_A + (u32)(wm + (lane & 15))*272 + (u32)(lane >> 4)*16;
    const u32 aad1 = aad0 + 16u*272;
    const u32 brow = (u32)(wn0 + (lane & 7) + ((lane >> 4) << 3));
    const u32 bof  = brow*272 + (u32)((lane >> 3) & 1)*16;   // col group 0 (+16*272 for group 1)

    // per-thread top-2 keys for each of the thread's 4 row-fragments
    u64 bst0[2][2], bst1[2][2];
    #pragma unroll
    for (int a = 0; a < 2; a++)
        #pragma unroll
        for (int b = 0; b < 2; b++) { bst0[a][b] = ~0ull; bst1[a][b] = ~0ull; }

    #pragma unroll 1
    for (int c = 0; c < NCH; c++) {
        if (c < NCH-1) asm volatile("cp.async.wait_group 1;" ::: "memory");
        else           asm volatile("cp.async.wait_group 0;" ::: "memory");
        __syncthreads();

        float acc[2][4][4];
        #pragma unroll
        for (int mf = 0; mf < 2; mf++)
            #pragma unroll
            for (int nf = 0; nf < 4; nf++)
                #pragma unroll
                for (int e = 0; e < 4; e++) acc[mf][nf][e] = 0.f;

        const u32 bufo = (u32)(c & 1) * APS;
        const u32 pb0 = sb + SM_B + bufo + bof;

        // fragment double-buffers (volatile asm keeps source order)
        u32 af[2][2][4], bf[2][2][4];
        ldsm4(af[0][0], aad0);
        ldsm4(af[0][1], aad1);
        ldsm4(bf[0][0], pb0);
        ldsm4(bf[0][1], pb0 + 16u*272);

        #pragma unroll
        for (int ks = 0; ks < 8; ks++) {
            const int cur = ks & 1, nxt = cur ^ 1;
            // prefetch next-ks fragments first; 8 MMAs below cover their latency
            if (ks < 7) {
                ldsm4(af[nxt][0], aad0 + (u32)(ks+1)*32);
                ldsm4(af[nxt][1], aad1 + (u32)(ks+1)*32);
                ldsm4(bf[nxt][0], pb0 + (u32)(ks+1)*32);
                ldsm4(bf[nxt][1], pb0 + 16u*272 + (u32)(ks+1)*32);
            }
            mma16816(acc[0][0], af[cur][0], bf[cur][0][0], bf[cur][0][1]);
            mma16816(acc[0][1], af[cur][0], bf[cur][0][2], bf[cur][0][3]);
            mma16816(acc[0][2], af[cur][0], bf[cur][1][0], bf[cur][1][1]);
            mma16816(acc[0][3], af[cur][0], bf[cur][1][2], bf[cur][1][3]);
            mma16816(acc[1][0], af[cur][1], bf[cur][0][0], bf[cur][0][1]);
            mma16816(acc[1][1], af[cur][1], bf[cur][0][2], bf[cur][0][3]);
            mma16816(acc[1][2], af[cur][1], bf[cur][1][0], bf[cur][1][1]);
            mma16816(acc[1][3], af[cur][1], bf[cur][1][2], bf[cur][1][3]);
        }

        // approx distances + running per-thread top-2 (u64 key: dist bits || idx)
        #pragma unroll
        for (int mf = 0; mf < 2; mf++)
            #pragma unroll
            for (int h = 0; h < 2; h++) {
                float z2v = z2s[wm + 16*mf + (lane >> 2) + 8*h];
                u64 b0k = bst0[mf][h], b1k = bst1[mf][h];
                #pragma unroll
                for (int nf = 0; nf < 4; nf++) {
                    int colg = c*CHN + wn0 + 8*nf + (lane & 3)*2;
                    #pragma unroll
                    for (int e = 0; e < 2; e++) {
                        float a = acc[mf][nf][2*h + e];
                        float dist = __fadd_rn(__fsub_rn(z2v, __fmul_rn(a, DSCL)), c2s[colg + e]);
                        u64 key = ((u64)__float_as_uint(dist) << 32) | (u32)(colg + e);
                        if (key < b1k) {
                            if (key < b0k) { b1k = b0k; b0k = key; }
                            else b1k = key;
                        }
                    }
                }
                bst0[mf][h] = b0k; bst1[mf][h] = b1k;
            }

        __syncthreads();                     // all warps done reading buf before refill
        if (c + 2 < NCH) {
            #pragma unroll
            for (int j = 0; j < 4; j++) {
                int i = tid + NTH*j;
                int r = i >> 4, sg = i & 15;
                u32 dst = sb + SM_B + bufo + (u32)r*272 + (u32)sg*16;
                cpa16(dst, (const char*)&g_cs[t][c+2][r][0] + sg*16);
            }
            asm volatile("cp.async.commit_group;" ::: "memory");
        }
    }

    // gather: 32 keys per row (16 threads x top-2), into dead B-buffer smem
    u64* cand = (u64*)(sm + SM_B);           // 128 rows * 32 keys = 32 KB
    #pragma unroll
    for (int mf = 0; mf < 2; mf++)
        #pragma unroll
        for (int h = 0; h < 2; h++) {
            int row = wm + 16*mf + 8*h + (lane >> 2);
            int slot = wc*8 + (lane & 3)*2;
            cand[row*32 + slot]     = bst0[mf][h];
            cand[row*32 + slot + 1] = bst1[mf][h];
        }
    __syncthreads();

    // resolve per row: find approx min, certify, exact-rescore candidates
    if (tid < TILE_B) {
        const int row = tid, b = b0 + row;
        const u64* ck = cand + row*32;
        u64 mn = ck[0];
        #pragma unroll
        for (int j = 1; j < 32; j++) if (ck[j] < mn) mn = ck[j];
        const float thr = __uint_as_float((u32)(mn >> 32)) + EPS;

        bool fb = false;
        #pragma unroll
        for (int p = 0; p < 16; p++)
            if (__uint_as_float((u32)(ck[2*p+1] >> 32)) <= thr) fb = true;

        if (fb) {
            int s = atomicAdd(fbn, 1);
            fbr[s] = row;
        } else {
            int ncand = 0;
            #pragma unroll
            for (int j = 0; j < 32; j++)
                if (__uint_as_float((u32)(ck[j] >> 32)) <= thr) ncand++;
            if (ncand <= 1) {
                bks[row] = (int)(mn & 0xffffffffu);
            } else {
                const float* zp = z_e + ((size_t)b*NT + t)*ND;
                const float z2 = z2s[row];
                u64 ebest = ~0ull;
                for (int j = 0; j < 32; j++) {
                    if (__uint_as_float((u32)(ck[j] >> 32)) > thr) continue;
                    int k = (int)(ck[j] & 0xffffffffu);
                    float ed = exact_dist(zp, cbk + ((size_t)t*NK + k)*ND, z2, c2s[k]);
                    u64 ek = ((u64)__float_as_uint(ed) << 32) | (u32)k;
                    if (ek < ebest) ebest = ek;
                }
                bks[row] = (int)(ebest & 0xffffffffu);
            }
        }
    }
    __syncthreads();

    // cooperative exact fallback for uncertified rows: 512 codes, 1/thread
    {
        const int nfb = *fbn;
        for (int f = 0; f < nfb; f++) {
            if (tid == 0) *fbb = ~0ull;
            __syncthreads();
            const int row = fbr[f], b = b0 + row;
            const float* zp = z_e + ((size_t)b*NT + t)*ND;
            const float z2 = z2s[row];
            const int k = tid;
            float ed = exact_dist(zp, cbk + ((size_t)t*NK + k)*ND, z2, c2s[k]);
            u64 loc = ((u64)__float_as_uint(ed) << 32) | (u32)k;
            #pragma unroll
            for (int off = 16; off >= 1; off >>= 1) {
                u64 o = __shfl_xor_sync(0xffffffffu, loc, off);
                if (o < loc) loc = o;
            }
            if (lane == 0) atomicMin(fbb, loc);
            __syncthreads();
            if (tid == 0) bks[row] = (int)(*fbb & 0xffffffffu);
            __syncthreads();
        }
    }
    __syncthreads();

    // tokens + usage
    if (tid < TILE_B) {
        int bk = bks[tid], b = b0 + tid;
        out[(size_t)NB*NT*ND + (size_t)b*NT + t] = (float)bk;
        g_used[t*NK + bk] = 1;
    }
    __syncthreads();

    // z_q_st + loss: 4 threads per row (32 floats each), R4-identical rounding
    {
        int row = tid >> 2, quad = tid & 3;
        int b = b0 + row, bk = bks[row];
        const float4* zr = (const float4*)(z_e + ((size_t)b*NT + t)*ND + quad*32);
        const float4* cr = (const float4*)(cbk + ((size_t)t*NK + bk)*ND + quad*32);
        float4* orow = (float4*)(out + ((size_t)b*NT + t)*ND + quad*32);
        double ls = 0.0;
        #pragma unroll
        for (int q = 0; q < 8; q++) {
            float4 zv = zr[q], cv = cr[q], ov;
            ov.x = __fadd_rn(zv.x, __fsub_rn(cv.x, zv.x)); { float d = __fsub_rn(zv.x, cv.x); ls += (double)__fmul_rn(d, d); }
            ov.y = __fadd_rn(zv.y, __fsub_rn(cv.y, zv.y)); { float d = __fsub_rn(zv.y, cv.y); ls += (double)__fmul_rn(d, d); }
            ov.z = __fadd_rn(zv.z, __fsub_rn(cv.z, zv.z)); { float d = __fsub_rn(zv.z, cv.z); ls += (double)__fmul_rn(d, d); }
            ov.w = __fadd_rn(zv.w, __fsub_rn(cv.w, zv.w)); { float d = __fsub_rn(zv.w, cv.w); ls += (double)__fmul_rn(d, d); }
            orow[q] = ov;
        }
        red[tid] = ls;
    }
    __syncthreads();
    for (int s = 256; s > 0; s >>= 1) {
        if (tid < s) red[tid] += red[tid + s];
        __syncthreads();
    }
    if (tid == 0) {
        long long q = __double2ll_rn(red[0] * LOSS_SCALE);
        atomicAdd(&g_loss, (u64)q);
    }
}

__global__ void vq_fin(float* __restrict__ out) {
    __shared__ int cnt[256];
    int tid = threadIdx.x;
    int c = 0;
    for (int i = tid; i < NT*NK; i += 256) c += g_used[i];
    cnt[tid] = c;
    __syncthreads();
    for (int s = 128; s > 0; s >>= 1) {
        if (tid < s) cnt[tid] += cnt[tid + s];
        __syncthreads();
    }
    if (tid == 0) {
        double ls = (double)g_loss / LOSS_SCALE;
        float vql = (float)(0.25 * ls / ((double)NB * NT * ND));
        size_t base = (size_t)NB*NT*ND + (size_t)NB*NT;
        out[base]     = vql;
        out[base + 1] = (float)cnt[0] / (float)(NT * NK);
    }
}

extern "C" void kernel_launch(void* const* d_in, const int* in_sizes, int n_in,
                              void* d_out, int out_size)
{
    const float* z_e = (const float*)d_in[0];   // (B, T, D) fp32
    const float* cbk = (const float*)d_in[1];   // (T, K, D) fp32
    float* out = (float*)d_out;

    cudaFuncSetAttribute(vq_main, cudaFuncAttributeMaxDynamicSharedMemorySize, SM_TOT);

    vq_prep<<<dim3(NCH, NT), 256>>>(cbk);
    vq_main<<<dim3(NBT, NT), NTH, SM_TOT>>>(z_e, cbk, out);
    vq_fin<<<1, 256>>>(out);
}